// round 2
// baseline (speedup 1.0000x reference)
#include <cuda_runtime.h>

// Problem constants (from setup_inputs)
constexpr int NN  = 20000;   // nodes
constexpr int TT  = 12;      // encoder steps
constexpr int HOR = 6;       // decoder horizon
constexpr int FF  = 16;      // input features (== C, decoder feedback)
constexpr int EE  = 320000;  // edges
constexpr int HH  = 128;     // hidden
constexpr int CC  = 16;      // out channels

// ---------------- scratch (static device globals; no allocation) -----------
__device__ __align__(16) float g_xw[NN * HH];    // x @ gcn_w (no bias)
__device__ __align__(16) float g_agg[NN * HH];   // neighbor aggregation
__device__ __align__(16) float g_hg[NN * HH];    // relu(gcn out)
__device__ __align__(16) float g_hb[3][NN * HH]; // rotating window buffers
__device__ float g_dinv[NN];                     // rsqrt(1 + in-degree)
__device__ int   g_deg[NN];
__device__ __align__(16) float g_W[384 * HH];    // fused [A;B;C] (384 x 128)
__device__ __align__(16) float g_dvec[HH];       // fused bias vector
__device__ int   g_is64;                         // edge index dtype flag

// ---------------- edge-index dtype detection --------------------------------
// If the buffer is int64 (values < 2^31), every odd 32-bit word is zero.
__global__ void k_detect(const unsigned int* __restrict__ w) {
    int nz = 0;
    #pragma unroll 8
    for (int i = 0; i < 128; ++i) nz += (w[2 * i + 1] != 0u);
    g_is64 = (nz == 0) ? 1 : 0;
}

__device__ __forceinline__ int load_idx(const void* p, long long e) {
    int v;
    if (g_is64) v = (int)((const long long*)p)[e];
    else        v = ((const int*)p)[e];
    // defensive clamp: never form an OOB address
    v = v < 0 ? 0 : (v >= NN ? NN - 1 : v);
    return v;
}

// ---------------- one-time prep: fold conv_w/proj_w into A,B,C -------------
// h_new = win1 @ A + win2 @ B + hg @ C + d
__global__ void k_prep_W(const float* __restrict__ conv_w,
                         const float* __restrict__ proj_w) {
    __shared__ float w0[128], w1[128], w2[128];
    int c = blockIdx.x;       // 0..383
    int h = threadIdx.x;      // 0..127
    float acc = 0.f;
    if (c < 128) {
        w1[h] = conv_w[((128 + h) * 128 + c) * 3 + 0];
        __syncthreads();
        #pragma unroll 4
        for (int o = 0; o < 128; ++o) acc += w1[o] * proj_w[h * 384 + 128 + o];
    } else if (c < 256) {
        int cc = c - 128;
        w0[h] = conv_w[(h * 128 + cc) * 3 + 0];
        __syncthreads();
        #pragma unroll 4
        for (int o = 0; o < 128; ++o) acc += w0[o] * proj_w[h * 384 + o];
    } else {
        int cc = c - 256;
        w0[h] = conv_w[(h * 128 + cc) * 3 + 1];
        w1[h] = conv_w[((128 + h) * 128 + cc) * 3 + 1];
        w2[h] = conv_w[((256 + h) * 128 + cc) * 3 + 1];
        __syncthreads();
        #pragma unroll 2
        for (int o = 0; o < 128; ++o) {
            acc += w0[o] * proj_w[h * 384 + o]
                 + w1[o] * proj_w[h * 384 + 128 + o]
                 + w2[o] * proj_w[h * 384 + 256 + o];
        }
    }
    g_W[c * 128 + h] = acc;
}

__global__ void k_prep_d(const float* __restrict__ conv_b,
                         const float* __restrict__ proj_w,
                         const float* __restrict__ proj_b) {
    int h = threadIdx.x;
    float acc = proj_b[h];
    #pragma unroll 4
    for (int j = 0; j < 384; ++j) acc += conv_b[j] * proj_w[h * 384 + j];
    g_dvec[h] = acc;
}

__global__ void k_zero_win() {
    int idx = blockIdx.x * blockDim.x + threadIdx.x;
    if (idx < NN * HH) { g_hb[0][idx] = 0.f; g_hb[1][idx] = 0.f; }
}

__global__ void k_zero_step() {
    int idx = blockIdx.x * blockDim.x + threadIdx.x;
    if (idx < NN * HH) g_agg[idx] = 0.f;
    if (idx < NN)      g_deg[idx] = 0;
}

// count in-degree from dst column; base = element offset of dst block
__global__ void k_count(const void* __restrict__ ei, long long base) {
    int e = blockIdx.x * blockDim.x + threadIdx.x;
    if (e < EE) atomicAdd(&g_deg[load_idx(ei, base + e)], 1);
}

__global__ void k_dinv() {
    int n = blockIdx.x * blockDim.x + threadIdx.x;
    if (n < NN) g_dinv[n] = rsqrtf(1.0f + (float)g_deg[n]);
}

// xw = x @ gcn_w      ([N,16] @ [16,128]); 16 rows per block, 128 threads
__global__ void k_xw(const float* __restrict__ x,
                     const float* __restrict__ gcn_w) {
    __shared__ float Ws[16 * 128];
    __shared__ float Xs[16 * 16];
    int tid  = threadIdx.x;
    int row0 = blockIdx.x * 16;
    #pragma unroll
    for (int i = 0; i < 16; ++i) Ws[i * 128 + tid] = gcn_w[i * 128 + tid];
    #pragma unroll
    for (int j = tid; j < 256; j += 128) Xs[j] = x[row0 * 16 + j];
    __syncthreads();
    #pragma unroll
    for (int r = 0; r < 16; ++r) {
        float acc = 0.f;
        #pragma unroll
        for (int f = 0; f < 16; ++f) acc += Xs[r * 16 + f] * Ws[f * 128 + tid];
        g_xw[(row0 + r) * 128 + tid] = acc;
    }
}

// scatter: agg[dst] += xw[src] * dinv[src] * dinv[dst]   (one warp per edge)
// base = element offset of src block; dst block is at base + EE
__global__ void k_scatter(const void* __restrict__ ei, long long base) {
    int warp = (blockIdx.x * blockDim.x + threadIdx.x) >> 5;
    int lane = threadIdx.x & 31;
    if (warp >= EE) return;
    int s = load_idx(ei, base + warp);
    int d = load_idx(ei, base + EE + warp);
    float coeff = g_dinv[s] * g_dinv[d];
    float4 v = reinterpret_cast<const float4*>(g_xw + s * 128)[lane];
    float* ag = g_agg + d * 128 + lane * 4;
    atomicAdd(ag + 0, v.x * coeff);
    atomicAdd(ag + 1, v.y * coeff);
    atomicAdd(ag + 2, v.z * coeff);
    atomicAdd(ag + 3, v.w * coeff);
}

// hg = relu(agg + xw * dinv^2 + gcn_b)
__global__ void k_hg(const float* __restrict__ gcn_b) {
    int idx = blockIdx.x * blockDim.x + threadIdx.x;
    if (idx < NN * HH) {
        int n = idx >> 7;
        float di = g_dinv[n];
        float v = g_agg[idx] + g_xw[idx] * di * di + gcn_b[idx & 127];
        g_hg[idx] = fmaxf(v, 0.f);
    }
}

// h_new = [win1 | win2 | hg] @ g_W + g_dvec
// block: 64 rows x 128 cols; 256 threads; thread = 8x4 register tile
__global__ void k_hnew(int i1, int i2, int idst) {
    __shared__ __align__(16) float In[64 * 32];
    __shared__ __align__(16) float Ws[32 * 128];
    int t    = threadIdx.x;
    int ty   = t >> 5;
    int tx   = t & 31;
    int row0 = blockIdx.x * 64;

    float acc[8][4];
    #pragma unroll
    for (int i = 0; i < 8; ++i)
        #pragma unroll
        for (int j = 0; j < 4; ++j) acc[i][j] = 0.f;

    #pragma unroll
    for (int kc = 0; kc < 12; ++kc) {
        const float* srcm = (kc < 4) ? g_hb[i1] : (kc < 8) ? g_hb[i2] : g_hg;
        int colbase = (kc & 3) * 32;
        #pragma unroll
        for (int i = 0; i < 8; ++i) {
            int L = t + 256 * i;
            int r = L >> 5, c = L & 31;
            int row = row0 + r;
            In[L] = (row < NN) ? srcm[row * 128 + colbase + c] : 0.f;
        }
        #pragma unroll
        for (int i = 0; i < 16; ++i) {
            int L = t + 256 * i;
            Ws[L] = g_W[kc * 4096 + L];
        }
        __syncthreads();
        #pragma unroll
        for (int k = 0; k < 32; ++k) {
            float4 w = *reinterpret_cast<float4*>(&Ws[k * 128 + tx * 4]);
            #pragma unroll
            for (int i = 0; i < 8; ++i) {
                float a = In[(ty + 8 * i) * 32 + k];
                acc[i][0] += a * w.x;
                acc[i][1] += a * w.y;
                acc[i][2] += a * w.z;
                acc[i][3] += a * w.w;
            }
        }
        __syncthreads();
    }

    float4 dv = *reinterpret_cast<float4*>(&g_dvec[tx * 4]);
    #pragma unroll
    for (int i = 0; i < 8; ++i) {
        int row = row0 + ty + 8 * i;
        if (row < NN) {
            float4 o;
            o.x = acc[i][0] + dv.x;
            o.y = acc[i][1] + dv.y;
            o.z = acc[i][2] + dv.z;
            o.w = acc[i][3] + dv.w;
            *reinterpret_cast<float4*>(&g_hb[idst][row * 128 + tx * 4]) = o;
        }
    }
}

// y = h_new @ head_w^T + head_b  -> d_out slice (also decoder feedback input)
__global__ void k_y(int isrc, const float* __restrict__ head_w,
                    const float* __restrict__ head_b,
                    float* __restrict__ out) {
    __shared__ float Hs[16][132];
    __shared__ float Ws[16][132];
    int t    = threadIdx.x;   // 256
    int row0 = blockIdx.x * 16;
    for (int i = t; i < 16 * 128; i += 256) Ws[i >> 7][i & 127] = head_w[i];
    for (int i = t; i < 16 * 128; i += 256) {
        int r = i >> 7;
        Hs[r][i & 127] = g_hb[isrc][(row0 + r) * 128 + (i & 127)];
    }
    __syncthreads();
    int r = t >> 4, c = t & 15;
    float acc = head_b[c];
    #pragma unroll 8
    for (int k = 0; k < 128; ++k) acc += Hs[r][k] * Ws[c][k];
    out[(row0 + r) * 16 + c] = acc;
}

// ---------------------------------------------------------------------------
extern "C" void kernel_launch(void* const* d_in, const int* in_sizes, int n_in,
                              void* d_out, int out_size) {
    const float* x_seq  = (const float*)d_in[0];
    const void*  ei     = d_in[1];                 // [T,2,E] int64 OR int32
    // d_in[2]=edge_attr_seq, d_in[3]=mask_seq, d_in[4]=id_seq  (unused)
    const float* gcn_w  = (const float*)d_in[5];
    const float* gcn_b  = (const float*)d_in[6];
    const float* conv_w = (const float*)d_in[7];
    const float* conv_b = (const float*)d_in[8];
    const float* proj_w = (const float*)d_in[9];
    const float* proj_b = (const float*)d_in[10];
    const float* head_w = (const float*)d_in[11];
    const float* head_b = (const float*)d_in[12];
    float* out = (float*)d_out;

    k_detect<<<1, 1>>>((const unsigned int*)ei);
    k_prep_W<<<384, 128>>>(conv_w, proj_w);
    k_prep_d<<<1, 128>>>(conv_b, proj_w, proj_b);
    k_zero_win<<<(NN * HH + 255) / 256, 256>>>();

    int i1 = 0, i2 = 1, idst = 2;
    for (int t = 0; t < TT + HOR; ++t) {
        bool enc = (t < TT);
        int  et  = enc ? t : (TT - 1);              // decoder reuses last edges
        long long base = (long long)et * 2 * EE;    // element offset of src col

        const float* xin;
        if (enc)            xin = x_seq + (long long)t * NN * FF;
        else if (t == TT)   xin = x_seq + (long long)(TT - 1) * NN * FF;
        else                xin = out + (long long)(t - TT - 1) * NN * CC;

        k_zero_step<<<(NN * HH + 255) / 256, 256>>>();
        if (enc) {
            k_count<<<(EE + 255) / 256, 256>>>(ei, base + EE);
            k_dinv<<<(NN + 255) / 256, 256>>>();
        }
        k_xw<<<NN / 16, 128>>>(xin, gcn_w);
        k_scatter<<<EE / 8, 256>>>(ei, base);       // 1 warp/edge
        k_hg<<<(NN * HH + 255) / 256, 256>>>(gcn_b);
        k_hnew<<<(NN + 63) / 64, 256>>>(i1, i2, idst);
        if (!enc)
            k_y<<<NN / 16, 256>>>(idst, head_w, head_b,
                                  out + (long long)(t - TT) * NN * CC);

        int old1 = i1; i1 = i2; i2 = idst; idst = old1;
    }
}

// round 3
// speedup vs baseline: 1.4851x; 1.4851x over previous
#include <cuda_runtime.h>

// Problem constants (from setup_inputs)
constexpr int NN  = 20000;   // nodes
constexpr int TT  = 12;      // encoder steps
constexpr int HOR = 6;       // decoder horizon
constexpr int FF  = 16;      // input features (== C, decoder feedback)
constexpr int EE  = 320000;  // edges
constexpr int HH  = 128;     // hidden
constexpr int CC  = 16;      // out channels

// ---------------- scratch (static device globals; no allocation) -----------
__device__ __align__(16) float g_xw[NN * HH];    // x @ gcn_w (no bias)
__device__ __align__(16) float g_agg[NN * HH];   // agg (seeded with self-loop term)
__device__ __align__(16) float g_hb[3][NN * HH]; // rotating window buffers
__device__ float g_dinv[NN];                     // rsqrt(1 + in-degree)
__device__ int   g_deg[NN];
__device__ __align__(16) float g_W[384 * HH];    // fused [A;B;C] (384 x 128)
__device__ __align__(16) float g_dvec[HH];       // fused bias vector
__device__ int   g_is64;                         // edge index dtype flag

// ---------------- edge-index dtype detection --------------------------------
__global__ void k_detect(const unsigned int* __restrict__ w) {
    int nz = 0;
    #pragma unroll 8
    for (int i = 0; i < 128; ++i) nz += (w[2 * i + 1] != 0u);
    g_is64 = (nz == 0) ? 1 : 0;
}

__device__ __forceinline__ int load_idx(const void* p, long long e) {
    int v;
    if (g_is64) v = (int)((const long long*)p)[e];
    else        v = ((const int*)p)[e];
    v = v < 0 ? 0 : (v >= NN ? NN - 1 : v);
    return v;
}

// ---------------- one-time prep: fold conv_w/proj_w into A,B,C -------------
// h_new = win1 @ A + win2 @ B + hg @ C + d
__global__ void k_prep_W(const float* __restrict__ conv_w,
                         const float* __restrict__ proj_w) {
    __shared__ float w0[128], w1[128], w2[128];
    int c = blockIdx.x;       // 0..383
    int h = threadIdx.x;      // 0..127
    float acc = 0.f;
    if (c < 128) {
        w1[h] = conv_w[((128 + h) * 128 + c) * 3 + 0];
        __syncthreads();
        #pragma unroll 4
        for (int o = 0; o < 128; ++o) acc += w1[o] * proj_w[h * 384 + 128 + o];
    } else if (c < 256) {
        int cc = c - 128;
        w0[h] = conv_w[(h * 128 + cc) * 3 + 0];
        __syncthreads();
        #pragma unroll 4
        for (int o = 0; o < 128; ++o) acc += w0[o] * proj_w[h * 384 + o];
    } else {
        int cc = c - 256;
        w0[h] = conv_w[(h * 128 + cc) * 3 + 1];
        w1[h] = conv_w[((128 + h) * 128 + cc) * 3 + 1];
        w2[h] = conv_w[((256 + h) * 128 + cc) * 3 + 1];
        __syncthreads();
        #pragma unroll 2
        for (int o = 0; o < 128; ++o) {
            acc += w0[o] * proj_w[h * 384 + o]
                 + w1[o] * proj_w[h * 384 + 128 + o]
                 + w2[o] * proj_w[h * 384 + 256 + o];
        }
    }
    g_W[c * 128 + h] = acc;
}

__global__ void k_prep_d(const float* __restrict__ conv_b,
                         const float* __restrict__ proj_w,
                         const float* __restrict__ proj_b) {
    int h = threadIdx.x;
    float acc = proj_b[h];
    #pragma unroll 4
    for (int j = 0; j < 384; ++j) acc += conv_b[j] * proj_w[h * 384 + j];
    g_dvec[h] = acc;
}

__global__ void k_zero_win() {
    int idx = blockIdx.x * blockDim.x + threadIdx.x;
    if (idx < NN * HH) { g_hb[0][idx] = 0.f; g_hb[1][idx] = 0.f; }
}

__global__ void k_zero_deg() {
    int n = blockIdx.x * blockDim.x + threadIdx.x;
    if (n < NN) g_deg[n] = 0;
}

__global__ void k_count(const void* __restrict__ ei, long long base) {
    int e = blockIdx.x * blockDim.x + threadIdx.x;
    if (e < EE) atomicAdd(&g_deg[load_idx(ei, base + e)], 1);
}

__global__ void k_dinv() {
    int n = blockIdx.x * blockDim.x + threadIdx.x;
    if (n < NN) g_dinv[n] = rsqrtf(1.0f + (float)g_deg[n]);
}

// xw = x @ gcn_w  AND  agg seed = xw*dinv^2 + gcn_b  (fused; saves two passes)
__global__ void k_xw(const float* __restrict__ x,
                     const float* __restrict__ gcn_w,
                     const float* __restrict__ gcn_b) {
    __shared__ float Ws[16 * 128];
    __shared__ float Xs[16 * 16];
    int tid  = threadIdx.x;             // 0..127 = output col
    int row0 = blockIdx.x * 16;
    #pragma unroll
    for (int i = 0; i < 16; ++i) Ws[i * 128 + tid] = gcn_w[i * 128 + tid];
    #pragma unroll
    for (int j = tid; j < 256; j += 128) Xs[j] = x[row0 * 16 + j];
    __syncthreads();
    float b = gcn_b[tid];
    #pragma unroll
    for (int r = 0; r < 16; ++r) {
        float acc = 0.f;
        #pragma unroll
        for (int f = 0; f < 16; ++f) acc += Xs[r * 16 + f] * Ws[f * 128 + tid];
        int row = row0 + r;
        float di = g_dinv[row];
        g_xw[row * 128 + tid]  = acc;
        g_agg[row * 128 + tid] = acc * di * di + b;
    }
}

// scatter: agg[dst] += xw[src]*dinv[src]*dinv[dst]  — one warp/edge, v4 red
__global__ void k_scatter(const void* __restrict__ ei, long long base) {
    int warp = (blockIdx.x * blockDim.x + threadIdx.x) >> 5;
    int lane = threadIdx.x & 31;
    if (warp >= EE) return;
    int s = load_idx(ei, base + warp);
    int d = load_idx(ei, base + EE + warp);
    float c = g_dinv[s] * g_dinv[d];
    float4 v = __ldg(reinterpret_cast<const float4*>(g_xw + s * 128) + lane);
    float* ag = g_agg + d * 128 + lane * 4;
    asm volatile("red.global.add.v4.f32 [%0], {%1, %2, %3, %4};"
                 :: "l"(ag), "f"(v.x * c), "f"(v.y * c),
                    "f"(v.z * c), "f"(v.w * c)
                 : "memory");
}

// h_new = [win1 | win2 | relu(agg)] @ g_W + g_dvec
// block: 64 rows x 128 cols; 256 threads; thread = 8x4 register tile
__global__ void k_hnew(int i1, int i2, int idst) {
    __shared__ __align__(16) float In[64 * 32];
    __shared__ __align__(16) float Ws[32 * 128];
    int t    = threadIdx.x;
    int ty   = t >> 5;
    int tx   = t & 31;
    int row0 = blockIdx.x * 64;

    float acc[8][4];
    #pragma unroll
    for (int i = 0; i < 8; ++i)
        #pragma unroll
        for (int j = 0; j < 4; ++j) acc[i][j] = 0.f;

    #pragma unroll
    for (int kc = 0; kc < 12; ++kc) {
        const float* srcm = (kc < 4) ? g_hb[i1] : (kc < 8) ? g_hb[i2] : g_agg;
        bool  do_relu = (kc >= 8);
        int colbase = (kc & 3) * 32;
        #pragma unroll
        for (int i = 0; i < 8; ++i) {
            int L = t + 256 * i;
            int r = L >> 5, c = L & 31;
            int row = row0 + r;
            float v = (row < NN) ? srcm[row * 128 + colbase + c] : 0.f;
            In[L] = do_relu ? fmaxf(v, 0.f) : v;
        }
        #pragma unroll
        for (int i = 0; i < 16; ++i) {
            int L = t + 256 * i;
            Ws[L] = g_W[kc * 4096 + L];
        }
        __syncthreads();
        #pragma unroll
        for (int k = 0; k < 32; ++k) {
            float4 w = *reinterpret_cast<float4*>(&Ws[k * 128 + tx * 4]);
            #pragma unroll
            for (int i = 0; i < 8; ++i) {
                float a = In[(ty + 8 * i) * 32 + k];
                acc[i][0] += a * w.x;
                acc[i][1] += a * w.y;
                acc[i][2] += a * w.z;
                acc[i][3] += a * w.w;
            }
        }
        __syncthreads();
    }

    float4 dv = *reinterpret_cast<float4*>(&g_dvec[tx * 4]);
    #pragma unroll
    for (int i = 0; i < 8; ++i) {
        int row = row0 + ty + 8 * i;
        if (row < NN) {
            float4 o;
            o.x = acc[i][0] + dv.x;
            o.y = acc[i][1] + dv.y;
            o.z = acc[i][2] + dv.z;
            o.w = acc[i][3] + dv.w;
            *reinterpret_cast<float4*>(&g_hb[idst][row * 128 + tx * 4]) = o;
        }
    }
}

// y = h_new @ head_w^T + head_b  -> d_out slice (also decoder feedback input)
__global__ void k_y(int isrc, const float* __restrict__ head_w,
                    const float* __restrict__ head_b,
                    float* __restrict__ out) {
    __shared__ float Hs[16][132];
    __shared__ float Ws[16][132];
    int t    = threadIdx.x;   // 256
    int row0 = blockIdx.x * 16;
    for (int i = t; i < 16 * 128; i += 256) Ws[i >> 7][i & 127] = head_w[i];
    for (int i = t; i < 16 * 128; i += 256) {
        int r = i >> 7;
        Hs[r][i & 127] = g_hb[isrc][(row0 + r) * 128 + (i & 127)];
    }
    __syncthreads();
    int r = t >> 4, c = t & 15;
    float acc = head_b[c];
    #pragma unroll 8
    for (int k = 0; k < 128; ++k) acc += Hs[r][k] * Ws[c][k];
    out[(row0 + r) * 16 + c] = acc;
}

// ---------------------------------------------------------------------------
extern "C" void kernel_launch(void* const* d_in, const int* in_sizes, int n_in,
                              void* d_out, int out_size) {
    const float* x_seq  = (const float*)d_in[0];
    const void*  ei     = d_in[1];                 // [T,2,E] int64 OR int32
    const float* gcn_w  = (const float*)d_in[5];
    const float* gcn_b  = (const float*)d_in[6];
    const float* conv_w = (const float*)d_in[7];
    const float* conv_b = (const float*)d_in[8];
    const float* proj_w = (const float*)d_in[9];
    const float* proj_b = (const float*)d_in[10];
    const float* head_w = (const float*)d_in[11];
    const float* head_b = (const float*)d_in[12];
    float* out = (float*)d_out;

    k_detect<<<1, 1>>>((const unsigned int*)ei);
    k_prep_W<<<384, 128>>>(conv_w, proj_w);
    k_prep_d<<<1, 128>>>(conv_b, proj_w, proj_b);
    k_zero_win<<<(NN * HH + 255) / 256, 256>>>();

    int i1 = 0, i2 = 1, idst = 2;
    for (int t = 0; t < TT + HOR; ++t) {
        bool enc = (t < TT);
        int  et  = enc ? t : (TT - 1);              // decoder reuses last edges
        long long base = (long long)et * 2 * EE;    // element offset of src col

        const float* xin;
        if (enc)            xin = x_seq + (long long)t * NN * FF;
        else if (t == TT)   xin = x_seq + (long long)(TT - 1) * NN * FF;
        else                xin = out + (long long)(t - TT - 1) * NN * CC;

        if (enc) {
            k_zero_deg<<<(NN + 255) / 256, 256>>>();
            k_count<<<(EE + 255) / 256, 256>>>(ei, base + EE);
            k_dinv<<<(NN + 255) / 256, 256>>>();
        }
        k_xw<<<NN / 16, 128>>>(xin, gcn_w, gcn_b);
        k_scatter<<<EE / 8, 256>>>(ei, base);       // 1 warp/edge, v4 red
        k_hnew<<<(NN + 63) / 64, 256>>>(i1, i2, idst);
        if (!enc)
            k_y<<<NN / 16, 256>>>(idst, head_w, head_b,
                                  out + (long long)(t - TT) * NN * CC);

        int old1 = i1; i1 = i2; i2 = idst; idst = old1;
    }
}

// round 4
// speedup vs baseline: 1.7877x; 1.2038x over previous
#include <cuda_runtime.h>

constexpr int NN  = 20000;   // nodes
constexpr int TT  = 12;      // encoder steps
constexpr int HOR = 6;       // decoder horizon
constexpr int FF  = 16;      // input features (== C, decoder feedback)
constexpr int EE  = 320000;  // edges
constexpr int HH  = 128;     // hidden
constexpr int CC  = 16;      // out channels

// ---------------- scratch (static device globals; no allocation) -----------
__device__ __align__(16) float g_xw[NN * HH];    // x @ gcn_w
__device__ __align__(16) float g_agg[NN * HH];   // gcn pre-relu output
__device__ __align__(16) float g_hb[3][NN * HH]; // rotating window buffers
__device__ __align__(16) float g_W[384 * HH];    // fused [A;B;C]
__device__ __align__(16) float g_dvec[HH];       // fused bias vector
__device__ int   g_is64;                         // edge index dtype flag

// per-edge-set CSR (built once per launch)
__device__ int   g_deg[TT][NN];
__device__ int   g_indptr[TT][NN + 1];
__device__ int   g_cur[TT][NN];
__device__ float g_dinv[TT][NN];
__device__ int   g_csrc[TT][EE];                 // src per csr slot
__device__ float g_cw[TT][EE];                   // dinv[s]*dinv[d] per slot

// ---------------- edge-index dtype detection --------------------------------
__global__ void k_detect(const unsigned int* __restrict__ w) {
    int nz = 0;
    #pragma unroll 8
    for (int i = 0; i < 128; ++i) nz += (w[2 * i + 1] != 0u);
    g_is64 = (nz == 0) ? 1 : 0;
}

__device__ __forceinline__ int load_idx(const void* p, long long e) {
    int v;
    if (g_is64) v = (int)((const long long*)p)[e];
    else        v = ((const int*)p)[e];
    v = v < 0 ? 0 : (v >= NN ? NN - 1 : v);
    return v;
}

// ---------------- one-time prep: fold conv_w/proj_w into A,B,C -------------
__global__ void k_prep_W(const float* __restrict__ conv_w,
                         const float* __restrict__ proj_w) {
    __shared__ float w0[128], w1[128], w2[128];
    int c = blockIdx.x;       // 0..383
    int h = threadIdx.x;      // 0..127
    float acc = 0.f;
    if (c < 128) {
        w1[h] = conv_w[((128 + h) * 128 + c) * 3 + 0];
        __syncthreads();
        #pragma unroll 4
        for (int o = 0; o < 128; ++o) acc += w1[o] * proj_w[h * 384 + 128 + o];
    } else if (c < 256) {
        int cc = c - 128;
        w0[h] = conv_w[(h * 128 + cc) * 3 + 0];
        __syncthreads();
        #pragma unroll 4
        for (int o = 0; o < 128; ++o) acc += w0[o] * proj_w[h * 384 + o];
    } else {
        int cc = c - 256;
        w0[h] = conv_w[(h * 128 + cc) * 3 + 1];
        w1[h] = conv_w[((128 + h) * 128 + cc) * 3 + 1];
        w2[h] = conv_w[((256 + h) * 128 + cc) * 3 + 1];
        __syncthreads();
        #pragma unroll 2
        for (int o = 0; o < 128; ++o) {
            acc += w0[o] * proj_w[h * 384 + o]
                 + w1[o] * proj_w[h * 384 + 128 + o]
                 + w2[o] * proj_w[h * 384 + 256 + o];
        }
    }
    g_W[c * 128 + h] = acc;
}

__global__ void k_prep_d(const float* __restrict__ conv_b,
                         const float* __restrict__ proj_w,
                         const float* __restrict__ proj_b) {
    int h = threadIdx.x;
    float acc = proj_b[h];
    #pragma unroll 4
    for (int j = 0; j < 384; ++j) acc += conv_b[j] * proj_w[h * 384 + j];
    g_dvec[h] = acc;
}

__global__ void k_zero_win() {
    int idx = blockIdx.x * blockDim.x + threadIdx.x;
    if (idx < NN * HH) { g_hb[0][idx] = 0.f; g_hb[1][idx] = 0.f; }
}

// ---------------- CSR construction (once per launch) ------------------------
__global__ void k_zero_deg12() {
    int idx = blockIdx.x * blockDim.x + threadIdx.x;
    if (idx < TT * NN) (&g_deg[0][0])[idx] = 0;
}

__global__ void k_count12(const void* __restrict__ ei) {
    long long idx = (long long)blockIdx.x * blockDim.x + threadIdx.x;
    if (idx >= (long long)TT * EE) return;
    int set = (int)(idx / EE);
    int e   = (int)(idx % EE);
    int d = load_idx(ei, (long long)set * 2 * EE + EE + e);
    atomicAdd(&g_deg[set][d], 1);
}

// one block per edge set: exclusive scan of degrees; emit indptr/cur/dinv
__global__ void k_scan12() {
    __shared__ int sh[1024];
    int set = blockIdx.x;
    int t   = threadIdx.x;
    const int PER = 20;                       // 1024*20 = 20480 >= NN
    int base = t * PER;
    int degs[PER];
    int sum = 0;
    #pragma unroll
    for (int i = 0; i < PER; ++i) {
        int n = base + i;
        degs[i] = (n < NN) ? g_deg[set][n] : 0;
        sum += degs[i];
    }
    sh[t] = sum;
    __syncthreads();
    // Hillis-Steele inclusive scan over 1024 partials
    for (int off = 1; off < 1024; off <<= 1) {
        int v = (t >= off) ? sh[t - off] : 0;
        __syncthreads();
        sh[t] += v;
        __syncthreads();
    }
    int run = sh[t] - sum;                    // exclusive prefix
    #pragma unroll
    for (int i = 0; i < PER; ++i) {
        int n = base + i;
        if (n < NN) {
            g_indptr[set][n] = run;
            g_cur[set][n]    = run;
            g_dinv[set][n]   = rsqrtf(1.0f + (float)degs[i]);
            run += degs[i];
        }
    }
    if (t == 1023) g_indptr[set][NN] = sh[1023];
}

__global__ void k_fill12(const void* __restrict__ ei) {
    long long idx = (long long)blockIdx.x * blockDim.x + threadIdx.x;
    if (idx >= (long long)TT * EE) return;
    int set = (int)(idx / EE);
    int e   = (int)(idx % EE);
    long long b = (long long)set * 2 * EE;
    int s = load_idx(ei, b + e);
    int d = load_idx(ei, b + EE + e);
    int pos = atomicAdd(&g_cur[set][d], 1);
    g_csrc[set][pos] = s;
    g_cw[set][pos]   = g_dinv[set][s] * g_dinv[set][d];
}

// ---------------- per-step kernels ------------------------------------------
// xw = x @ gcn_w      ([N,16] @ [16,128]); 16 rows per block, 128 threads
__global__ void k_xw(const float* __restrict__ x,
                     const float* __restrict__ gcn_w) {
    __shared__ float Ws[16 * 128];
    __shared__ float Xs[16 * 16];
    int tid  = threadIdx.x;
    int row0 = blockIdx.x * 16;
    #pragma unroll
    for (int i = 0; i < 16; ++i) Ws[i * 128 + tid] = gcn_w[i * 128 + tid];
    #pragma unroll
    for (int j = tid; j < 256; j += 128) Xs[j] = x[row0 * 16 + j];
    __syncthreads();
    #pragma unroll
    for (int r = 0; r < 16; ++r) {
        float acc = 0.f;
        #pragma unroll
        for (int f = 0; f < 16; ++f) acc += Xs[r * 16 + f] * Ws[f * 128 + tid];
        g_xw[(row0 + r) * 128 + tid] = acc;
    }
}

// CSR gather: agg[n] = sum_e w_e * xw[src_e] + dinv[n]^2 * xw[n] + gcn_b
// one warp per node; atomic-free, single coalesced row write
__global__ void k_gather(int set, const float* __restrict__ gcn_b) {
    int warp = (blockIdx.x * blockDim.x + threadIdx.x) >> 5;
    int lane = threadIdx.x & 31;
    if (warp >= NN) return;
    int node = warp;
    int beg = g_indptr[set][node];
    int end = g_indptr[set][node + 1];
    float di = g_dinv[set][node];
    float4 acc = __ldg(reinterpret_cast<const float4*>(g_xw + node * 128) + lane);
    float d2 = di * di;
    acc.x *= d2; acc.y *= d2; acc.z *= d2; acc.w *= d2;
    int i = beg;
    for (; i + 1 < end; i += 2) {
        int   s0 = g_csrc[set][i],     s1 = g_csrc[set][i + 1];
        float w0 = g_cw[set][i],       w1 = g_cw[set][i + 1];
        float4 u0 = __ldg(reinterpret_cast<const float4*>(g_xw + s0 * 128) + lane);
        float4 u1 = __ldg(reinterpret_cast<const float4*>(g_xw + s1 * 128) + lane);
        acc.x += u0.x * w0 + u1.x * w1;
        acc.y += u0.y * w0 + u1.y * w1;
        acc.z += u0.z * w0 + u1.z * w1;
        acc.w += u0.w * w0 + u1.w * w1;
    }
    if (i < end) {
        int   s0 = g_csrc[set][i];
        float w0 = g_cw[set][i];
        float4 u0 = __ldg(reinterpret_cast<const float4*>(g_xw + s0 * 128) + lane);
        acc.x += u0.x * w0; acc.y += u0.y * w0;
        acc.z += u0.z * w0; acc.w += u0.w * w0;
    }
    float4 b = __ldg(reinterpret_cast<const float4*>(gcn_b) + lane);
    acc.x += b.x; acc.y += b.y; acc.z += b.z; acc.w += b.w;
    *(reinterpret_cast<float4*>(g_agg + node * 128) + lane) = acc;
}

// h_new = [win1 | win2 | relu(agg)] @ g_W + g_dvec
__global__ void k_hnew(int i1, int i2, int idst) {
    __shared__ __align__(16) float In[64 * 32];
    __shared__ __align__(16) float Ws[32 * 128];
    int t    = threadIdx.x;
    int ty   = t >> 5;
    int tx   = t & 31;
    int row0 = blockIdx.x * 64;

    float acc[8][4];
    #pragma unroll
    for (int i = 0; i < 8; ++i)
        #pragma unroll
        for (int j = 0; j < 4; ++j) acc[i][j] = 0.f;

    #pragma unroll
    for (int kc = 0; kc < 12; ++kc) {
        const float* srcm = (kc < 4) ? g_hb[i1] : (kc < 8) ? g_hb[i2] : g_agg;
        bool  do_relu = (kc >= 8);
        int colbase = (kc & 3) * 32;
        #pragma unroll
        for (int i = 0; i < 8; ++i) {
            int L = t + 256 * i;
            int r = L >> 5, c = L & 31;
            int row = row0 + r;
            float v = (row < NN) ? srcm[row * 128 + colbase + c] : 0.f;
            In[L] = do_relu ? fmaxf(v, 0.f) : v;
        }
        #pragma unroll
        for (int i = 0; i < 16; ++i) {
            int L = t + 256 * i;
            Ws[L] = g_W[kc * 4096 + L];
        }
        __syncthreads();
        #pragma unroll
        for (int k = 0; k < 32; ++k) {
            float4 w = *reinterpret_cast<float4*>(&Ws[k * 128 + tx * 4]);
            #pragma unroll
            for (int i = 0; i < 8; ++i) {
                float a = In[(ty + 8 * i) * 32 + k];
                acc[i][0] += a * w.x;
                acc[i][1] += a * w.y;
                acc[i][2] += a * w.z;
                acc[i][3] += a * w.w;
            }
        }
        __syncthreads();
    }

    float4 dv = *reinterpret_cast<float4*>(&g_dvec[tx * 4]);
    #pragma unroll
    for (int i = 0; i < 8; ++i) {
        int row = row0 + ty + 8 * i;
        if (row < NN) {
            float4 o;
            o.x = acc[i][0] + dv.x;
            o.y = acc[i][1] + dv.y;
            o.z = acc[i][2] + dv.z;
            o.w = acc[i][3] + dv.w;
            *reinterpret_cast<float4*>(&g_hb[idst][row * 128 + tx * 4]) = o;
        }
    }
}

// y = h_new @ head_w^T + head_b  -> d_out slice (also decoder feedback input)
__global__ void k_y(int isrc, const float* __restrict__ head_w,
                    const float* __restrict__ head_b,
                    float* __restrict__ out) {
    __shared__ float Hs[16][132];
    __shared__ float Ws[16][132];
    int t    = threadIdx.x;   // 256
    int row0 = blockIdx.x * 16;
    for (int i = t; i < 16 * 128; i += 256) Ws[i >> 7][i & 127] = head_w[i];
    for (int i = t; i < 16 * 128; i += 256) {
        int r = i >> 7;
        Hs[r][i & 127] = g_hb[isrc][(row0 + r) * 128 + (i & 127)];
    }
    __syncthreads();
    int r = t >> 4, c = t & 15;
    float acc = head_b[c];
    #pragma unroll 8
    for (int k = 0; k < 128; ++k) acc += Hs[r][k] * Ws[c][k];
    out[(row0 + r) * 16 + c] = acc;
}

// ---------------------------------------------------------------------------
extern "C" void kernel_launch(void* const* d_in, const int* in_sizes, int n_in,
                              void* d_out, int out_size) {
    const float* x_seq  = (const float*)d_in[0];
    const void*  ei     = d_in[1];                 // [T,2,E] int64 OR int32
    const float* gcn_w  = (const float*)d_in[5];
    const float* gcn_b  = (const float*)d_in[6];
    const float* conv_w = (const float*)d_in[7];
    const float* conv_b = (const float*)d_in[8];
    const float* proj_w = (const float*)d_in[9];
    const float* proj_b = (const float*)d_in[10];
    const float* head_w = (const float*)d_in[11];
    const float* head_b = (const float*)d_in[12];
    float* out = (float*)d_out;

    // ---- one-time prep ----
    k_detect<<<1, 1>>>((const unsigned int*)ei);
    k_prep_W<<<384, 128>>>(conv_w, proj_w);
    k_prep_d<<<1, 128>>>(conv_b, proj_w, proj_b);
    k_zero_win<<<(NN * HH + 255) / 256, 256>>>();
    k_zero_deg12<<<(TT * NN + 255) / 256, 256>>>();
    {
        long long tot = (long long)TT * EE;
        int blocks = (int)((tot + 255) / 256);
        k_count12<<<blocks, 256>>>(ei);
        k_scan12<<<TT, 1024>>>();
        k_fill12<<<blocks, 256>>>(ei);
    }

    // ---- time loop ----
    int i1 = 0, i2 = 1, idst = 2;
    for (int t = 0; t < TT + HOR; ++t) {
        bool enc = (t < TT);
        int  set = enc ? t : (TT - 1);              // decoder reuses last edges

        const float* xin;
        if (enc)            xin = x_seq + (long long)t * NN * FF;
        else if (t == TT)   xin = nullptr;          // reuse encoder step-11 agg
        else                xin = out + (long long)(t - TT - 1) * NN * CC;

        if (xin) {                                  // skip at t == TT (identical GCN)
            k_xw<<<NN / 16, 128>>>(xin, gcn_w);
            k_gather<<<(NN * 32 + 255) / 256, 256>>>(set, gcn_b);
        }
        k_hnew<<<(NN + 63) / 64, 256>>>(i1, i2, idst);
        if (!enc)
            k_y<<<NN / 16, 256>>>(idst, head_w, head_b,
                                  out + (long long)(t - TT) * NN * CC);

        int old1 = i1; i1 = i2; i2 = idst; idst = old1;
    }
}